// round 7
// baseline (speedup 1.0000x reference)
#include <cuda_runtime.h>
#include <cstdint>
#include <cstddef>

// Problem constants (fixed by the reference).
#define Bb   2
#define Hh   16
#define Ss   2048
#define Dd   64
#define TQ   16          // queries per CTA
#define TK   8           // keys per k-tile
#define NKT  (Ss / TK)   // 256 k-tiles
#define NTH  512         // 16 heads x 16 queries x 2 d-halves

typedef unsigned long long u64;

// Padded smem row layout for K/V tiles (conflict-free 16B broadcast loads).
#define ROWP      (TK * Dd + 4)        // 516 floats per head per buffer
#define KVBUF     (Hh * ROWP)          // 8256 floats per buffer
#define SSH_HSTR  (TQ * 9)             // 144: 9-stride kills the q*8 bank pattern

__device__ __forceinline__ void ffma2(u64& acc, u64 a, u64 b) {
    asm volatile("fma.rn.f32x2 %0, %1, %2, %0;" : "+l"(acc) : "l"(a), "l"(b));
}
__device__ __forceinline__ u64 mul2(u64 a, u64 b) {
    u64 r; asm("mul.rn.f32x2 %0, %1, %2;" : "=l"(r) : "l"(a), "l"(b)); return r;
}
__device__ __forceinline__ u64 pack2(float lo, float hi) {
    u64 r; asm("mov.b64 %0, {%1,%2};" : "=l"(r) : "f"(lo), "f"(hi)); return r;
}
__device__ __forceinline__ void unpack2(u64 v, float& lo, float& hi) {
    asm("mov.b64 {%0,%1}, %2;" : "=f"(lo), "=f"(hi) : "l"(v));
}
__device__ __forceinline__ void cp16(float* sdst, const float* gsrc) {
    uint32_t sa = (uint32_t)__cvta_generic_to_shared(sdst);
    asm volatile("cp.async.cg.shared.global [%0], [%1], 16;" :: "r"(sa), "l"(gsrc));
}
__device__ __forceinline__ void cp_commit() { asm volatile("cp.async.commit_group;"); }
template <int N>
__device__ __forceinline__ void cp_wait() { asm volatile("cp.async.wait_group %0;" :: "n"(N)); }

__device__ __forceinline__ float neg_inf() { return __int_as_float(0xff800000); }

// ---------------------------------------------------------------------------
// Mask storage detection (harness normalizes dtypes; bool is not a wire type).
// Only the ELEMENT SIZE matters downstream: "masked" == nonzero bits.
// ---------------------------------------------------------------------------
__device__ int g_mask_esz;   // 1, 2, or 4 bytes per mask element

#define F_BYTE_HI  1
#define F_NOT01B   2
#define F_NOTF32   4
#define F_NOTBF16  8

__global__ void detect_mask_kernel(const uint32_t* __restrict__ m, int nwords) {
    __shared__ int sflags;
    if (threadIdx.x == 0) sflags = 0;
    __syncthreads();
    int f = 0;
    for (int i = threadIdx.x; i < nwords; i += blockDim.x) {
        uint32_t w = m[i];
        if (w & 0xFFFFFF00u) f |= F_BYTE_HI;
        #pragma unroll
        for (int j = 0; j < 4; j++) {
            uint32_t byt = (w >> (8 * j)) & 0xffu;
            if (byt > 1u) f |= F_NOT01B;
        }
        if (w != 0u && w != 0x3f800000u) f |= F_NOTF32;
        uint32_t lo = w & 0xffffu, hi = w >> 16;
        if ((lo != 0u && lo != 0x3f80u) || (hi != 0u && hi != 0x3f80u)) f |= F_NOTBF16;
    }
    atomicOr(&sflags, f);
    __syncthreads();
    if (threadIdx.x == 0) {
        int ff = sflags;
        int esz;
        if (!(ff & F_BYTE_HI))      esz = 4;  // int32 0/1
        else if (!(ff & F_NOT01B))  esz = 1;  // byte-packed bool
        else if (!(ff & F_NOTF32))  esz = 4;  // float32 0/1
        else if (!(ff & F_NOTBF16)) esz = 2;  // bf16
        else                        esz = 1;  // fallback
        g_mask_esz = esz;
    }
}

// smem (floats): Kb[2*KVBUF] | Vb[2*KVBUF] | Ssh[16*144] | Msh[144] | Rsh[144]
#define SMEM_FLOATS (2 * KVBUF + 2 * KVBUF + Hh * SSH_HSTR + SSH_HSTR + SSH_HSTR)

__global__ void __launch_bounds__(NTH, 1)
attn_head_softmax_kernel(const float* __restrict__ Qg,
                         const float* __restrict__ Kg,
                         const float* __restrict__ Vg,
                         const unsigned char* __restrict__ Mg,
                         float* __restrict__ Og)
{
    extern __shared__ float smem[];
    float* Kb  = smem;                       // 2 * 8256
    float* Vb  = Kb + 2 * KVBUF;             // 2 * 8256
    float* Ssh = Vb + 2 * KVBUF;             // 16 * 144
    float* Msh = Ssh + Hh * SSH_HSTR;        // 144
    float* Rsh = Msh + SSH_HSTR;             // 144

    const int b  = blockIdx.y;
    const int q0 = blockIdx.x * TQ;
    const int t  = threadIdx.x;
    const int h  = t >> 5;           // warp id == head (0..15)
    const int q  = (t >> 1) & 15;    // 0..15
    const int dh = t & 1;            // d-half: dims [dh*32, dh*32+32)

    const int esz = g_mask_esz;      // uniform

    // ---- this thread's 32 Q dims, pre-scaled by 1/sqrt(64), packed f32x2 ----
    u64 Qp[16];
    {
        const ulonglong2* qg = reinterpret_cast<const ulonglong2*>(
            Qg + ((size_t)(b * Hh + h) * Ss + (q0 + q)) * Dd + dh * 32);
        const u64 sc = pack2(0.125f, 0.125f);
        #pragma unroll
        for (int i = 0; i < 8; i++) {
            ulonglong2 v = qg[i];
            Qp[2*i]   = mul2(v.x, sc);
            Qp[2*i+1] = mul2(v.y, sc);
        }
    }

    // ---- context accumulator: 32 fp32 as 16 packed f32x2 ----
    u64 ctx[16];
    #pragma unroll
    for (int i = 0; i < 16; i++) ctx[i] = 0ull;

    // Mask row base in BYTES (only dh==0 threads touch it).
    const unsigned char* mrow =
        Mg + ((size_t)(b * Hh + h) * Ss + (q0 + q)) * (size_t)Ss * (size_t)esz;

    // ---- K/V tile loader: 2048 float4 per matrix, 4 per thread each ----
    auto load_tile = [&](int kt, int buf) {
        const int k0 = kt * TK;
        #pragma unroll
        for (int j = 0; j < 4; j++) {
            int i   = t + j * NTH;     // 0..2047
            int row = i >> 4;          // h2*TK + kk
            int d4  = i & 15;
            int h2  = row >> 3;
            int kk  = row & 7;
            size_t goff = ((size_t)(b * Hh + h2) * Ss + (k0 + kk)) * Dd + d4 * 4;
            int soff = buf * KVBUF + h2 * ROWP + kk * Dd + d4 * 4;
            cp16(&Kb[soff], Kg + goff);
            cp16(&Vb[soff], Vg + goff);
        }
    };

    load_tile(0, 0);
    cp_commit();

    for (int kt = 0; kt < NKT; kt++) {
        const int buf = kt & 1;
        cp_wait<0>();          // tile kt resident in buf
        __syncthreads();       // (A) K/V visible; also proves all threads done
                               //     reading buf^1 (last read was iter kt-1)
        if (kt + 1 < NKT) { load_tile(kt + 1, buf ^ 1); cp_commit(); }

        const int k0 = kt * TK;

        // ---- 8 mask flags for keys k0..k0+7 (dh==0 threads only) ----
        unsigned mk = 0;
        if (dh == 0) {
            if (esz == 4) {
                const uint4* p = reinterpret_cast<const uint4*>(mrow + (size_t)k0 * 4);
                uint4 a = p[0], c = p[1];
                mk = (a.x ? 1u : 0u) | (a.y ? 2u : 0u) | (a.z ? 4u : 0u) | (a.w ? 8u : 0u)
                   | (c.x ? 16u : 0u) | (c.y ? 32u : 0u) | (c.z ? 64u : 0u) | (c.w ? 128u : 0u);
            } else if (esz == 1) {
                u64 v = *reinterpret_cast<const u64*>(mrow + k0);
                #pragma unroll
                for (int j = 0; j < 8; j++)
                    if ((v >> (8 * j)) & 0xffull) mk |= (1u << j);
            } else { // esz == 2
                uint4 a = *reinterpret_cast<const uint4*>(mrow + (size_t)k0 * 2);
                uint32_t w[4] = {a.x, a.y, a.z, a.w};
                #pragma unroll
                for (int j = 0; j < 4; j++) {
                    if (w[j] & 0xffffu)   mk |= (1u << (2 * j));
                    if (w[j] >> 16)       mk |= (1u << (2 * j + 1));
                }
            }
        }

        // ---- scores: partial dot over this thread's 32 dims, combine via shfl ----
        float sreg[TK];
        #pragma unroll
        for (int kk = 0; kk < TK; kk++) {
            const ulonglong2* kr = reinterpret_cast<const ulonglong2*>(
                &Kb[buf * KVBUF + h * ROWP + kk * Dd + dh * 32]);
            u64 a0 = 0ull, a1 = 0ull;     // 2-way split chains (8 deep each)
            #pragma unroll
            for (int i = 0; i < 8; i++) {
                ulonglong2 kv = kr[i];
                ffma2(a0, Qp[2*i],   kv.x);
                ffma2(a1, Qp[2*i+1], kv.y);
            }
            float l0, h0, l1, h1; unpack2(a0, l0, h0); unpack2(a1, l1, h1);
            float part = (l0 + h0) + (l1 + h1);
            // Fold mask into the dh==0 partial: -inf survives the butterfly add.
            if ((mk >> kk) & 1u) part = neg_inf();
            float s = part + __shfl_xor_sync(0xffffffffu, part, 1);
            sreg[kk] = s;
            if (dh == 0) Ssh[h * SSH_HSTR + q * 9 + kk] = s;
        }
        __syncthreads();       // (B) Ssh ready

        // ---- head softmax: 128 threads, one (q,kk) each, reduce over 16 h ----
        if (t < TQ * TK) {
            const int q2 = t >> 3, kk2 = t & 7;
            const int base = q2 * 9 + kk2;
            float m = neg_inf();
            #pragma unroll
            for (int h2 = 0; h2 < Hh; h2++) m = fmaxf(m, Ssh[h2 * SSH_HSTR + base]);
            float mm, inv;
            if (m == neg_inf()) { mm = 0.f; inv = 0.f; }
            else {
                float sum = 0.f;
                #pragma unroll
                for (int h2 = 0; h2 < Hh; h2++)
                    sum += __expf(Ssh[h2 * SSH_HSTR + base] - m);
                mm = m; inv = 1.0f / sum;
            }
            Msh[base] = mm;
            Rsh[base] = inv;
        }
        __syncthreads();       // (C) Msh/Rsh ready

        // ---- context accumulate: ctx += w * V (this thread's 32 dims) ----
        #pragma unroll
        for (int kk = 0; kk < TK; kk++) {
            const int base = q * 9 + kk;
            float w = __expf(sreg[kk] - Msh[base]) * Rsh[base];
            u64 wp = pack2(w, w);
            const ulonglong2* vr = reinterpret_cast<const ulonglong2*>(
                &Vb[buf * KVBUF + h * ROWP + kk * Dd + dh * 32]);
            #pragma unroll
            for (int i = 0; i < 8; i++) {
                ulonglong2 vv = vr[i];
                ffma2(ctx[2*i],   wp, vv.x);
                ffma2(ctx[2*i+1], wp, vv.y);
            }
        }
        // no barrier here: next iteration's (A) covers the buf-reuse hazard
    }

    // ---- epilogue: out[b, q0+q, h, dh*32 + :] = ctx ----
    ulonglong2* og = reinterpret_cast<ulonglong2*>(
        Og + ((size_t)(b * Ss + (q0 + q)) * Hh + h) * Dd + dh * 32);
    #pragma unroll
    for (int i = 0; i < 8; i++) {
        ulonglong2 v; v.x = ctx[2*i]; v.y = ctx[2*i+1];
        og[i] = v;
    }
}

extern "C" void kernel_launch(void* const* d_in, const int* in_sizes, int n_in,
                              void* d_out, int out_size) {
    const float*         Q = (const float*)d_in[0];
    const float*         K = (const float*)d_in[1];
    const float*         V = (const float*)d_in[2];
    const unsigned char* M = (const unsigned char*)d_in[3];   // mask, dtype detected on-device
    // d_in[4] = head_dim (compile-time 64); unused.
    float* O = (float*)d_out;

    // 1) classify mask storage (element size). 256 KB sample, deterministic.
    detect_mask_kernel<<<1, 256>>>((const uint32_t*)M, 1 << 16);

    // 2) main attention kernel
    const size_t smem_bytes = (size_t)SMEM_FLOATS * sizeof(float);  // ~143 KB
    cudaFuncSetAttribute(attn_head_softmax_kernel,
                         cudaFuncAttributeMaxDynamicSharedMemorySize,
                         (int)smem_bytes);

    dim3 grid(Ss / TQ, Bb);   // (128, 2) = 256 CTAs of 512 threads
    attn_head_softmax_kernel<<<grid, NTH, smem_bytes>>>(Q, K, V, M, O);
}

// round 8
// speedup vs baseline: 1.4542x; 1.4542x over previous
#include <cuda_runtime.h>
#include <cstdint>
#include <cstddef>

// Problem constants (fixed by the reference).
#define Bb   2
#define Hh   16
#define Ss   2048
#define Dd   64
#define TQ   16          // queries per CTA
#define TK   8           // keys per k-tile
#define NKT  (Ss / TK)   // 256 k-tiles
#define NTH  512         // 16 heads x 16 queries x 2 d-halves

typedef unsigned long long u64;

// Padded smem row layout for K/V tiles (conflict-free 16B broadcast loads).
#define ROWP      (TK * Dd + 4)        // 516 floats per head per buffer
#define KVBUF     (Hh * ROWP)          // 8256 floats per buffer
#define SSH_HSTR  (TQ * 9)             // 144: 9-stride kills the q*8 bank pattern

__device__ __forceinline__ void ffma2(u64& acc, u64 a, u64 b) {
    asm volatile("fma.rn.f32x2 %0, %1, %2, %0;" : "+l"(acc) : "l"(a), "l"(b));
}
__device__ __forceinline__ u64 mul2(u64 a, u64 b) {
    u64 r; asm("mul.rn.f32x2 %0, %1, %2;" : "=l"(r) : "l"(a), "l"(b)); return r;
}
__device__ __forceinline__ u64 pack2(float lo, float hi) {
    u64 r; asm("mov.b64 %0, {%1,%2};" : "=l"(r) : "f"(lo), "f"(hi)); return r;
}
__device__ __forceinline__ void unpack2(u64 v, float& lo, float& hi) {
    asm("mov.b64 {%0,%1}, %2;" : "=f"(lo), "=f"(hi) : "l"(v));
}
__device__ __forceinline__ void cp16(float* sdst, const float* gsrc) {
    uint32_t sa = (uint32_t)__cvta_generic_to_shared(sdst);
    asm volatile("cp.async.cg.shared.global [%0], [%1], 16;" :: "r"(sa), "l"(gsrc));
}
__device__ __forceinline__ void cp_commit() { asm volatile("cp.async.commit_group;"); }
template <int N>
__device__ __forceinline__ void cp_wait() { asm volatile("cp.async.wait_group %0;" :: "n"(N)); }

__device__ __forceinline__ float neg_inf() { return __int_as_float(0xff800000); }

// ---------------------------------------------------------------------------
// Mask storage detection (harness normalizes dtypes; bool is not a wire type).
// Only the ELEMENT SIZE matters downstream: "masked" == nonzero bits.
// ---------------------------------------------------------------------------
__device__ int g_mask_esz;   // 1, 2, or 4 bytes per mask element

#define F_BYTE_HI  1
#define F_NOT01B   2
#define F_NOTF32   4
#define F_NOTBF16  8

__global__ void detect_mask_kernel(const uint32_t* __restrict__ m, int nwords) {
    __shared__ int sflags;
    if (threadIdx.x == 0) sflags = 0;
    __syncthreads();
    int f = 0;
    for (int i = threadIdx.x; i < nwords; i += blockDim.x) {
        uint32_t w = m[i];
        if (w & 0xFFFFFF00u) f |= F_BYTE_HI;
        #pragma unroll
        for (int j = 0; j < 4; j++) {
            uint32_t byt = (w >> (8 * j)) & 0xffu;
            if (byt > 1u) f |= F_NOT01B;
        }
        if (w != 0u && w != 0x3f800000u) f |= F_NOTF32;
        uint32_t lo = w & 0xffffu, hi = w >> 16;
        if ((lo != 0u && lo != 0x3f80u) || (hi != 0u && hi != 0x3f80u)) f |= F_NOTBF16;
    }
    atomicOr(&sflags, f);
    __syncthreads();
    if (threadIdx.x == 0) {
        int ff = sflags;
        int esz;
        if (!(ff & F_BYTE_HI))      esz = 4;  // int32 0/1
        else if (!(ff & F_NOT01B))  esz = 1;  // byte-packed bool
        else if (!(ff & F_NOTF32))  esz = 4;  // float32 0/1
        else if (!(ff & F_NOTBF16)) esz = 2;  // bf16
        else                        esz = 1;  // fallback
        g_mask_esz = esz;
    }
}

// smem (floats): Kb[2*KVBUF] | Vb[2*KVBUF] | Ssh[16*144] | MRsh[144 float2]
#define SMEM_FLOATS (2 * KVBUF + 2 * KVBUF + Hh * SSH_HSTR + 2 * SSH_HSTR)

__global__ void __launch_bounds__(NTH, 1)
attn_head_softmax_kernel(const float* __restrict__ Qg,
                         const float* __restrict__ Kg,
                         const float* __restrict__ Vg,
                         const unsigned char* __restrict__ Mg,
                         float* __restrict__ Og)
{
    extern __shared__ float smem[];
    float*  Kb   = smem;                       // 2 * 8256
    float*  Vb   = Kb + 2 * KVBUF;             // 2 * 8256
    float*  Ssh  = Vb + 2 * KVBUF;             // 16 * 144
    float2* MRsh = reinterpret_cast<float2*>(Ssh + Hh * SSH_HSTR);   // 144 float2

    const int b  = blockIdx.y;
    const int q0 = blockIdx.x * TQ;
    const int t  = threadIdx.x;
    const int h  = t >> 5;           // warp id == head (0..15)
    const int q  = (t >> 1) & 15;    // 0..15
    const int dh = t & 1;            // d-split: INTERLEAVED 16B chunks
    const int dhb = dh * 16;         // byte offset of this thread's chunk in a 32B pair

    const int esz = g_mask_esz;      // uniform

    // ---- this thread's 32 Q dims (chunks i*32B + dhb), pre-scaled by 1/8 ----
    u64 Qp[16];
    {
        const char* qbase = reinterpret_cast<const char*>(
            Qg + ((size_t)(b * Hh + h) * Ss + (q0 + q)) * Dd);
        const u64 sc = pack2(0.125f, 0.125f);
        #pragma unroll
        for (int i = 0; i < 8; i++) {
            ulonglong2 v = *reinterpret_cast<const ulonglong2*>(qbase + i * 32 + dhb);
            Qp[2*i]   = mul2(v.x, sc);
            Qp[2*i+1] = mul2(v.y, sc);
        }
    }

    // ---- context accumulator: 32 fp32 as 16 packed f32x2 ----
    u64 ctx[16];
    #pragma unroll
    for (int i = 0; i < 16; i++) ctx[i] = 0ull;

    // Mask row base in BYTES (only dh==0 threads touch it).
    const unsigned char* mrow =
        Mg + ((size_t)(b * Hh + h) * Ss + (q0 + q)) * (size_t)Ss * (size_t)esz;

    // ---- K/V tile loader: 2048 float4 per matrix, 4 per thread each ----
    auto load_tile = [&](int kt, int buf) {
        const int k0 = kt * TK;
        #pragma unroll
        for (int j = 0; j < 4; j++) {
            int i   = t + j * NTH;     // 0..2047
            int row = i >> 4;          // h2*TK + kk
            int d4  = i & 15;
            int h2  = row >> 3;
            int kk  = row & 7;
            size_t goff = ((size_t)(b * Hh + h2) * Ss + (k0 + kk)) * Dd + d4 * 4;
            int soff = buf * KVBUF + h2 * ROWP + kk * Dd + d4 * 4;
            cp16(&Kb[soff], Kg + goff);
            cp16(&Vb[soff], Vg + goff);
        }
    };

    load_tile(0, 0);
    cp_commit();

    for (int kt = 0; kt < NKT; kt++) {
        const int buf = kt & 1;
        cp_wait<0>();          // tile kt resident in buf
        __syncthreads();       // (A) K/V visible; also proves all threads done
                               //     reading buf^1 (last read was iter kt-1)
        if (kt + 1 < NKT) { load_tile(kt + 1, buf ^ 1); cp_commit(); }

        const int k0 = kt * TK;

        // ---- 8 mask flags for keys k0..k0+7 (dh==0 threads only) ----
        unsigned mk = 0;
        if (dh == 0) {
            if (esz == 4) {
                const uint4* p = reinterpret_cast<const uint4*>(mrow + (size_t)k0 * 4);
                uint4 a = p[0], c = p[1];
                mk = (a.x ? 1u : 0u) | (a.y ? 2u : 0u) | (a.z ? 4u : 0u) | (a.w ? 8u : 0u)
                   | (c.x ? 16u : 0u) | (c.y ? 32u : 0u) | (c.z ? 64u : 0u) | (c.w ? 128u : 0u);
            } else if (esz == 1) {
                u64 v = *reinterpret_cast<const u64*>(mrow + k0);
                #pragma unroll
                for (int j = 0; j < 8; j++)
                    if ((v >> (8 * j)) & 0xffull) mk |= (1u << j);
            } else { // esz == 2
                uint4 a = *reinterpret_cast<const uint4*>(mrow + (size_t)k0 * 2);
                uint32_t w[4] = {a.x, a.y, a.z, a.w};
                #pragma unroll
                for (int j = 0; j < 4; j++) {
                    if (w[j] & 0xffffu)   mk |= (1u << (2 * j));
                    if (w[j] >> 16)       mk |= (1u << (2 * j + 1));
                }
            }
        }

        // ---- scores: partial dot over this thread's 32 dims, combine via shfl ----
        float sreg[TK];
        #pragma unroll
        for (int kk = 0; kk < TK; kk++) {
            const char* kb = reinterpret_cast<const char*>(
                &Kb[buf * KVBUF + h * ROWP + kk * Dd]);
            u64 a0 = 0ull, a1 = 0ull;     // 2-way split chains (8 deep each)
            #pragma unroll
            for (int i = 0; i < 8; i++) {
                ulonglong2 kv = *reinterpret_cast<const ulonglong2*>(kb + i * 32 + dhb);
                ffma2(a0, Qp[2*i],   kv.x);
                ffma2(a1, Qp[2*i+1], kv.y);
            }
            float l0, h0, l1, h1; unpack2(a0, l0, h0); unpack2(a1, l1, h1);
            float part = (l0 + h0) + (l1 + h1);
            // Fold mask into the dh==0 partial: -inf survives the butterfly add.
            if ((mk >> kk) & 1u) part = neg_inf();
            float s = part + __shfl_xor_sync(0xffffffffu, part, 1);
            sreg[kk] = s;
            if (dh == 0) Ssh[h * SSH_HSTR + q * 9 + kk] = s;
        }
        __syncthreads();       // (B) Ssh ready

        // ---- head softmax: 128 threads, one (q,kk) each, reduce over 16 h ----
        if (t < TQ * TK) {
            const int q2 = t >> 3, kk2 = t & 7;
            const int base = q2 * 9 + kk2;
            float m = neg_inf();
            #pragma unroll
            for (int h2 = 0; h2 < Hh; h2++) m = fmaxf(m, Ssh[h2 * SSH_HSTR + base]);
            float mm, inv;
            if (m == neg_inf()) { mm = 0.f; inv = 0.f; }
            else {
                float sum = 0.f;
                #pragma unroll
                for (int h2 = 0; h2 < Hh; h2++)
                    sum += __expf(Ssh[h2 * SSH_HSTR + base] - m);
                mm = m; inv = 1.0f / sum;
            }
            MRsh[base] = make_float2(mm, inv);
        }
        __syncthreads();       // (C) MRsh ready

        // ---- context accumulate: ctx += w * V (this thread's 32 dims) ----
        #pragma unroll
        for (int kk = 0; kk < TK; kk++) {
            float2 mr = MRsh[q * 9 + kk];
            float w = __expf(sreg[kk] - mr.x) * mr.y;
            u64 wp = pack2(w, w);
            const char* vb = reinterpret_cast<const char*>(
                &Vb[buf * KVBUF + h * ROWP + kk * Dd]);
            #pragma unroll
            for (int i = 0; i < 8; i++) {
                ulonglong2 vv = *reinterpret_cast<const ulonglong2*>(vb + i * 32 + dhb);
                ffma2(ctx[2*i],   wp, vv.x);
                ffma2(ctx[2*i+1], wp, vv.y);
            }
        }
        // no barrier here: next iteration's (A) covers the buf-reuse hazard
    }

    // ---- epilogue: out[b, q0+q, h, chunks i*32B + dhb] = ctx ----
    char* obase = reinterpret_cast<char*>(
        Og + ((size_t)(b * Ss + (q0 + q)) * Hh + h) * Dd);
    #pragma unroll
    for (int i = 0; i < 8; i++) {
        ulonglong2 v; v.x = ctx[2*i]; v.y = ctx[2*i+1];
        *reinterpret_cast<ulonglong2*>(obase + i * 32 + dhb) = v;
    }
}

extern "C" void kernel_launch(void* const* d_in, const int* in_sizes, int n_in,
                              void* d_out, int out_size) {
    const float*         Q = (const float*)d_in[0];
    const float*         K = (const float*)d_in[1];
    const float*         V = (const float*)d_in[2];
    const unsigned char* M = (const unsigned char*)d_in[3];   // mask, dtype detected on-device
    // d_in[4] = head_dim (compile-time 64); unused.
    float* O = (float*)d_out;

    // 1) classify mask storage (element size). 256 KB sample, deterministic.
    detect_mask_kernel<<<1, 256>>>((const uint32_t*)M, 1 << 16);

    // 2) main attention kernel
    const size_t smem_bytes = (size_t)SMEM_FLOATS * sizeof(float);  // ~142 KB
    cudaFuncSetAttribute(attn_head_softmax_kernel,
                         cudaFuncAttributeMaxDynamicSharedMemorySize,
                         (int)smem_bytes);

    dim3 grid(Ss / TQ, Bb);   // (128, 2) = 256 CTAs of 512 threads
    attn_head_softmax_kernel<<<grid, NTH, smem_bytes>>>(Q, K, V, M, O);
}